// round 12
// baseline (speedup 1.0000x reference)
#include <cuda_runtime.h>
#include <cuda_bf16.h>

#define TT 512
#define H 8
#define NSM 148
#define BLK 128
#define GROUPS_PER_BLK (BLK / 8)

typedef unsigned long long u64;

__device__ __forceinline__ float tanhf_a(float x) {
    float y; asm("tanh.approx.f32 %0, %1;" : "=f"(y) : "f"(x)); return y;
}
__device__ __forceinline__ u64 pack2(float lo, float hi) {
    u64 r; asm("mov.b64 %0, {%1, %2};" : "=l"(r) : "f"(lo), "f"(hi)); return r;
}
__device__ __forceinline__ void unpack2(u64 v, float& lo, float& hi) {
    asm("mov.b64 {%0, %1}, %2;" : "=f"(lo), "=f"(hi) : "l"(v));
}
__device__ __forceinline__ u64 fma2(u64 a, u64 b, u64 c) {
    u64 r; asm("fma.rn.f32x2 %0, %1, %2, %3;" : "=l"(r) : "l"(a), "l"(b), "l"(c)); return r;
}
__device__ __forceinline__ u64 mul2(u64 a, u64 b) {
    u64 r; asm("mul.rn.f32x2 %0, %1, %2;" : "=l"(r) : "l"(a), "l"(b)); return r;
}
__device__ __forceinline__ u64 add2(u64 a, u64 b) {
    u64 r; asm("add.rn.f32x2 %0, %1, %2;" : "=l"(r) : "l"(a), "l"(b)); return r;
}
__device__ __forceinline__ float hsum2(u64 v) {
    float lo, hi; unpack2(v, lo, hi); return lo + hi;
}
__device__ __forceinline__ u64 d2u(double d) {
    return (u64)__double_as_longlong(d);
}

__global__ void __launch_bounds__(BLK, 1)
lstm2_kernel(const float* __restrict__ x,
             const float* __restrict__ W_ih1, const float* __restrict__ W_hh1,
             const float* __restrict__ b_ih1, const float* __restrict__ b_hh1,
             const float* __restrict__ W_ih2, const float* __restrict__ W_hh2,
             const float* __restrict__ b_ih2, const float* __restrict__ b_hh2,
             const float* __restrict__ W_fc,  const float* __restrict__ b_fc,
             float* __restrict__ out, int B)
{
    const int wg    = threadIdx.x >> 3;                      // group in block (0..15)
    const int n     = threadIdx.x & 7;                       // hidden unit of this lane
    const int group = blockIdx.x * GROUPS_PER_BLK + wg;      // global group id (pair id)
    const int nPair = B >> 1;                                // 2048 batch pairs
    const bool active = (group < nPair);
    const int bA = active ? (2 * group)     : 0;             // dummy groups replay batch 0/1
    const int bB = active ? (2 * group + 1) : 1;

    // ping-pong broadcast buffers: [parity][group][stream][unit]
    __shared__ __align__(16) float h1buf[2][GROUPS_PER_BLK][2][8];
    __shared__ __align__(16) float h2buf[2][GROUPS_PER_BLK][2][8];

    // sigmoid(z) = 0.5*tanh(0.5*z)+0.5 -> pre-scale sigmoid-gate rows by 0.5
    const float SS = 0.5f, SG = 1.0f;
    const int ri = n, rf = 8 + n, rg = 16 + n, ro = 24 + n;
    const u64 HALF2 = pack2(0.5f, 0.5f);

    // layer-1 x weights packed as (w, 0) so the x-term seeds the packed chain
    const u64 wxi2 = pack2(W_ih1[ri] * SS, 0.0f);
    const u64 wxf2 = pack2(W_ih1[rf] * SS, 0.0f);
    const u64 wxg2 = pack2(W_ih1[rg] * SG, 0.0f);
    const u64 wxo2 = pack2(W_ih1[ro] * SS, 0.0f);

    const u64 bi1 = pack2((b_ih1[ri] + b_hh1[ri]) * SS, 0.0f);
    const u64 bf1 = pack2((b_ih1[rf] + b_hh1[rf]) * SS, 0.0f);
    const u64 bg1 = pack2((b_ih1[rg] + b_hh1[rg]) * SG, 0.0f);
    const u64 bo1 = pack2((b_ih1[ro] + b_hh1[ro]) * SS, 0.0f);
    const u64 bi2 = pack2((b_ih2[ri] + b_hh2[ri]) * SS, 0.0f);
    const u64 bf2 = pack2((b_ih2[rf] + b_hh2[rf]) * SS, 0.0f);
    const u64 bg2 = pack2((b_ih2[rg] + b_hh2[rg]) * SG, 0.0f);
    const u64 bo2 = pack2((b_ih2[ro] + b_hh2[ro]) * SS, 0.0f);

    u64 whi1[4], whf1[4], whg1[4], who1[4];
    u64 wii2[4], wif2[4], wig2[4], wio2[4];
    u64 whi2[4], whf2[4], whg2[4], who2[4];
#pragma unroll
    for (int p = 0; p < 4; ++p) {
        const int k0 = 2*p, k1 = 2*p + 1;
        whi1[p] = pack2(W_hh1[ri*H + k0] * SS, W_hh1[ri*H + k1] * SS);
        whf1[p] = pack2(W_hh1[rf*H + k0] * SS, W_hh1[rf*H + k1] * SS);
        whg1[p] = pack2(W_hh1[rg*H + k0] * SG, W_hh1[rg*H + k1] * SG);
        who1[p] = pack2(W_hh1[ro*H + k0] * SS, W_hh1[ro*H + k1] * SS);
        wii2[p] = pack2(W_ih2[ri*H + k0] * SS, W_ih2[ri*H + k1] * SS);
        wif2[p] = pack2(W_ih2[rf*H + k0] * SS, W_ih2[rf*H + k1] * SS);
        wig2[p] = pack2(W_ih2[rg*H + k0] * SG, W_ih2[rg*H + k1] * SG);
        wio2[p] = pack2(W_ih2[ro*H + k0] * SS, W_ih2[ro*H + k1] * SS);
        whi2[p] = pack2(W_hh2[ri*H + k0] * SS, W_hh2[ri*H + k1] * SS);
        whf2[p] = pack2(W_hh2[rf*H + k0] * SS, W_hh2[rf*H + k1] * SS);
        whg2[p] = pack2(W_hh2[rg*H + k0] * SG, W_hh2[rg*H + k1] * SG);
        who2[p] = pack2(W_hh2[ro*H + k0] * SS, W_hh2[ro*H + k1] * SS);
    }

    const u64 Z = pack2(0.0f, 0.0f);
    u64 h1A[4], h2A[4], h1B[4], h2B[4];
#pragma unroll
    for (int p = 0; p < 4; ++p) { h1A[p]=Z; h2A[p]=Z; h1B[p]=Z; h2B[p]=Z; }
    u64 c12A = Z, c12B = Z;              // packed (c1, c2) per stream

    // Fused body: both streams' layer1(t) || layer2(t-1), ops interleaved for ILP
    auto step2 = [&](float xtA, float xtB, int par) {
        const u64 xA = pack2(xtA, 0.0f);
        const u64 xB = pack2(xtB, 0.0f);

        u64 viA = fma2(wxi2, xA, bi1), viB = fma2(wxi2, xB, bi1);
        u64 vfA = fma2(wxf2, xA, bf1), vfB = fma2(wxf2, xB, bf1);
        u64 vgA = fma2(wxg2, xA, bg1), vgB = fma2(wxg2, xB, bg1);
        u64 voA = fma2(wxo2, xA, bo1), voB = fma2(wxo2, xB, bo1);
        u64 iaA = bi2, faA = bf2, gaA = bg2, oaA = bo2;
        u64 iaB = bi2, faB = bf2, gaB = bg2, oaB = bo2;
        u64 ibA = Z, fbA = Z, gbA = Z, obA = Z;
        u64 ibB = Z, fbB = Z, gbB = Z, obB = Z;
#pragma unroll
        for (int p = 0; p < 4; ++p) {
            viA = fma2(whi1[p], h1A[p], viA);  viB = fma2(whi1[p], h1B[p], viB);
            vfA = fma2(whf1[p], h1A[p], vfA);  vfB = fma2(whf1[p], h1B[p], vfB);
            vgA = fma2(whg1[p], h1A[p], vgA);  vgB = fma2(whg1[p], h1B[p], vgB);
            voA = fma2(who1[p], h1A[p], voA);  voB = fma2(who1[p], h1B[p], voB);
            iaA = fma2(wii2[p], h1A[p], iaA);  iaB = fma2(wii2[p], h1B[p], iaB);
            faA = fma2(wif2[p], h1A[p], faA);  faB = fma2(wif2[p], h1B[p], faB);
            gaA = fma2(wig2[p], h1A[p], gaA);  gaB = fma2(wig2[p], h1B[p], gaB);
            oaA = fma2(wio2[p], h1A[p], oaA);  oaB = fma2(wio2[p], h1B[p], oaB);
            ibA = fma2(whi2[p], h2A[p], ibA);  ibB = fma2(whi2[p], h2B[p], ibB);
            fbA = fma2(whf2[p], h2A[p], fbA);  fbB = fma2(whf2[p], h2B[p], fbB);
            gbA = fma2(whg2[p], h2A[p], gbA);  gbB = fma2(whg2[p], h2B[p], gbB);
            obA = fma2(who2[p], h2A[p], obA);  obB = fma2(who2[p], h2B[p], obB);
        }
        const float aiA = hsum2(viA),              aiB = hsum2(viB);
        const float afA = hsum2(vfA),              afB = hsum2(vfB);
        const float agA = hsum2(vgA),              agB = hsum2(vgB);
        const float aoA = hsum2(voA),              aoB = hsum2(voB);
        const float a2iA = hsum2(add2(iaA, ibA)),  a2iB = hsum2(add2(iaB, ibB));
        const float a2fA = hsum2(add2(faA, fbA)),  a2fB = hsum2(add2(faB, fbB));
        const float a2gA = hsum2(add2(gaA, gbA)),  a2gB = hsum2(add2(gaB, gbB));
        const float a2oA = hsum2(add2(oaA, obA)),  a2oB = hsum2(add2(oaB, obB));

        const u64 PiA = pack2(tanhf_a(aiA), tanhf_a(a2iA));
        const u64 PiB = pack2(tanhf_a(aiB), tanhf_a(a2iB));
        const u64 PfA = pack2(tanhf_a(afA), tanhf_a(a2fA));
        const u64 PfB = pack2(tanhf_a(afB), tanhf_a(a2fB));
        const u64 PoA = pack2(tanhf_a(aoA), tanhf_a(a2oA));
        const u64 PoB = pack2(tanhf_a(aoB), tanhf_a(a2oB));
        const u64 PgA = pack2(tanhf_a(agA), tanhf_a(a2gA));
        const u64 PgB = pack2(tanhf_a(agB), tanhf_a(a2gB));

        const u64 giA = fma2(PiA, HALF2, HALF2), giB = fma2(PiB, HALF2, HALF2);
        const u64 gfA = fma2(PfA, HALF2, HALF2), gfB = fma2(PfB, HALF2, HALF2);
        const u64 goA = fma2(PoA, HALF2, HALF2), goB = fma2(PoB, HALF2, HALF2);

        c12A = fma2(gfA, c12A, mul2(giA, PgA));
        c12B = fma2(gfB, c12B, mul2(giB, PgB));
        float c1A_, c2A_; unpack2(c12A, c1A_, c2A_);
        float c1B_, c2B_; unpack2(c12B, c1B_, c2B_);
        const u64 PcA = pack2(tanhf_a(c1A_), tanhf_a(c2A_));
        const u64 PcB = pack2(tanhf_a(c1B_), tanhf_a(c2B_));
        const u64 h12A = mul2(goA, PcA);
        const u64 h12B = mul2(goB, PcB);
        float h1nA, h2nA; unpack2(h12A, h1nA, h2nA);
        float h1nB, h2nB; unpack2(h12B, h1nB, h2nB);

        // ---- SMEM broadcast: 4 STS + syncwarp + 8 LDS.128 ----
        h1buf[par][wg][0][n] = h1nA;  h1buf[par][wg][1][n] = h1nB;
        h2buf[par][wg][0][n] = h2nA;  h2buf[par][wg][1][n] = h2nB;
        __syncwarp();
        {
            const double2* rA1 = (const double2*)&h1buf[par][wg][0][0];
            const double2* rB1 = (const double2*)&h1buf[par][wg][1][0];
            const double2* rA2 = (const double2*)&h2buf[par][wg][0][0];
            const double2* rB2 = (const double2*)&h2buf[par][wg][1][0];
            double2 d0, d1;
            d0 = rA1[0]; d1 = rA1[1];
            h1A[0] = d2u(d0.x); h1A[1] = d2u(d0.y); h1A[2] = d2u(d1.x); h1A[3] = d2u(d1.y);
            d0 = rB1[0]; d1 = rB1[1];
            h1B[0] = d2u(d0.x); h1B[1] = d2u(d0.y); h1B[2] = d2u(d1.x); h1B[3] = d2u(d1.y);
            d0 = rA2[0]; d1 = rA2[1];
            h2A[0] = d2u(d0.x); h2A[1] = d2u(d0.y); h2A[2] = d2u(d1.x); h2A[3] = d2u(d1.y);
            d0 = rB2[0]; d1 = rB2[1];
            h2B[0] = d2u(d0.x); h2B[1] = d2u(d0.y); h2B[2] = d2u(d1.x); h2B[3] = d2u(d1.y);
        }
    };

    const float4* __restrict__ xrA = (const float4*)(x + (size_t)bA * TT);
    const float4* __restrict__ xrB = (const float4*)(x + (size_t)bB * TT);
    float4 curA = xrA[0], curB = xrB[0];
    float4 nxtA = xrA[1], nxtB = xrB[1];

    // prologue: first body computes layer1(0); its layer2(-1) output is junk
    step2(curA.x, curB.x, 0);
    {   // reset layer2 state (keep c1) in both streams
        float k1, kj;
        unpack2(c12A, k1, kj); c12A = pack2(k1, 0.0f);
        unpack2(c12B, k1, kj); c12B = pack2(k1, 0.0f);
    }
#pragma unroll
    for (int p = 0; p < 4; ++p) { h2A[p] = Z; h2B[p] = Z; }

    step2(curA.y, curB.y, 1);
    step2(curA.z, curB.z, 0);
    step2(curA.w, curB.w, 1);
    curA = nxtA; curB = nxtB;

    for (int t4 = 1; t4 < TT/4; ++t4) {
        const int nidx = (t4 + 1 < TT/4) ? (t4 + 1) : t4;
        nxtA = xrA[nidx]; nxtB = xrB[nidx];
        step2(curA.x, curB.x, 0);
        step2(curA.y, curB.y, 1);
        step2(curA.z, curB.z, 0);
        step2(curA.w, curB.w, 1);
        curA = nxtA; curB = nxtB;
    }

    // epilogue: one more body computes layer2(511); layer1(512) discarded
    step2(0.0f, 0.0f, 0);

    // ---------- final FC (8 -> 4) for both streams ----------
    if (active && n < 4) {
        u64 accA = pack2(b_fc[n], 0.0f);
        u64 accB = accA;
#pragma unroll
        for (int p = 0; p < 4; ++p) {
            const u64 w = pack2(W_fc[n*H + 2*p], W_fc[n*H + 2*p + 1]);
            accA = fma2(w, h2A[p], accA);
            accB = fma2(w, h2B[p], accB);
        }
        out[bA * 4 + n] = hsum2(accA);
        out[bB * 4 + n] = hsum2(accB);
    }
}

extern "C" void kernel_launch(void* const* d_in, const int* in_sizes, int n_in,
                              void* d_out, int out_size)
{
    const float* x     = (const float*)d_in[0];
    const float* W_ih1 = (const float*)d_in[1];
    const float* W_hh1 = (const float*)d_in[2];
    const float* b_ih1 = (const float*)d_in[3];
    const float* b_hh1 = (const float*)d_in[4];
    const float* W_ih2 = (const float*)d_in[5];
    const float* W_hh2 = (const float*)d_in[6];
    const float* b_ih2 = (const float*)d_in[7];
    const float* b_hh2 = (const float*)d_in[8];
    const float* W_fc  = (const float*)d_in[9];
    const float* b_fc  = (const float*)d_in[10];
    float* out = (float*)d_out;

    const int B = in_sizes[0] / TT;          // 4096
    // 148 blocks x 128 threads = 1 warp/SMSP on every SM; 2368 pair-slots
    // for 2048 batch pairs (surplus run dummies)
    int blocks = NSM;
    const int min_blocks = ((B / 2) * H + BLK - 1) / BLK;
    if (blocks < min_blocks) blocks = min_blocks;   // safety for other sizes

    lstm2_kernel<<<blocks, BLK>>>(x, W_ih1, W_hh1, b_ih1, b_hh1,
                                  W_ih2, W_hh2, b_ih2, b_hh2,
                                  W_fc, b_fc, out, B);
}